// round 8
// baseline (speedup 1.0000x reference)
#include <cuda_runtime.h>
#include <math.h>

// Fixed shapes: B=8,S=512,E=512,V=50000
#define V_TOTAL 50000
#define E_DIM   512
#define N_TOK   4096
#define VS      9          // vocab splits -> grid 9 x 32 = 288 blocks

#define BM 128
#define BN 128
#define BK 16
#define NKSTEP (E_DIM / BK)   // 32

#define BATCH_ELEMS (N_TOK * E_DIM)        // 2097152
#define EMB_ELEMS   (V_TOTAL * E_DIM)      // 25600000

// Scratch (device globals: allocation is forbidden in kernel_launch)
__device__ float g_pval[N_TOK * VS];
__device__ int   g_pidx[N_TOK * VS];

// ---------------------------------------------------------------------------
// Fused GEMM + emb-norm + running argmax, 2-stage smem double buffering.
// score(t,v) = (b_t . e_v) * rsqrt(||e_v||^2) == cos_sim * ||b_t||; the
// positive per-token factor ||b_t|| does not move the argmax, so batch
// normalization is elided. argmax(sim) == argmin(1 - sim) == reference.
// ---------------------------------------------------------------------------
__global__ __launch_bounds__(256, 2)
void score_kernel(const float* __restrict__ batch, const float* __restrict__ emb) {
    __shared__ float As[2][BK][BM];
    __shared__ float Bs[2][BK][BN];
    __shared__ float s_v[256 * 8];
    __shared__ int   s_i[256 * 8];

    const int vs  = blockIdx.x;          // vocab split
    const int tb  = blockIdx.y;          // token tile
    const int tid = threadIdx.x;
    const int tx  = tid & 15;            // column group (8 cols)
    const int ty  = tid >> 4;            // row group (8 rows)

    // per-thread load coordinates (2 float4 per thread per tile)
    const int l_row0 = (tid * 2)     >> 2;   // 0..127
    const int l_kq0  = (tid * 2)     & 3;    // float4 slot within BK
    const int l_row1 = (tid * 2 + 1) >> 2;
    const int l_kq1  = (tid * 2 + 1) & 3;

    const int split   = (V_TOTAL + VS - 1) / VS;       // 5556
    const int v_begin = vs * split;
    const int v_end   = min(v_begin + split, V_TOTAL);
    const int ntiles  = (v_end - v_begin + BN - 1) / BN;

    float bestv[8];
    int   besti[8];
#pragma unroll
    for (int i = 0; i < 8; ++i) { bestv[i] = -1e30f; besti[i] = 0; }

    const float* Abase = batch + (size_t)(tb * BM) * E_DIM;

    for (int nt = 0; nt < ntiles; ++nt) {
        const int v0 = v_begin + nt * BN;

        float acc[8][8];
        float bsq[8];
#pragma unroll
        for (int j = 0; j < 8; ++j) {
            bsq[j] = 0.f;
#pragma unroll
            for (int i = 0; i < 8; ++i) acc[i][j] = 0.f;
        }

        // ---- prologue: load K-step 0 into stage 0 ----
        {
            float4 a0 = reinterpret_cast<const float4*>(
                            Abase + (size_t)l_row0 * E_DIM)[l_kq0];
            float4 a1 = reinterpret_cast<const float4*>(
                            Abase + (size_t)l_row1 * E_DIM)[l_kq1];
            As[0][l_kq0 * 4 + 0][l_row0] = a0.x;
            As[0][l_kq0 * 4 + 1][l_row0] = a0.y;
            As[0][l_kq0 * 4 + 2][l_row0] = a0.z;
            As[0][l_kq0 * 4 + 3][l_row0] = a0.w;
            As[0][l_kq1 * 4 + 0][l_row1] = a1.x;
            As[0][l_kq1 * 4 + 1][l_row1] = a1.y;
            As[0][l_kq1 * 4 + 2][l_row1] = a1.z;
            As[0][l_kq1 * 4 + 3][l_row1] = a1.w;

            int vb0 = v0 + l_row0, vb1 = v0 + l_row1;
            float4 b0 = make_float4(0.f, 0.f, 0.f, 0.f);
            float4 b1 = make_float4(0.f, 0.f, 0.f, 0.f);
            if (vb0 < V_TOTAL)
                b0 = reinterpret_cast<const float4*>(emb + (size_t)vb0 * E_DIM)[l_kq0];
            if (vb1 < V_TOTAL)
                b1 = reinterpret_cast<const float4*>(emb + (size_t)vb1 * E_DIM)[l_kq1];
            Bs[0][l_kq0 * 4 + 0][l_row0] = b0.x;
            Bs[0][l_kq0 * 4 + 1][l_row0] = b0.y;
            Bs[0][l_kq0 * 4 + 2][l_row0] = b0.z;
            Bs[0][l_kq0 * 4 + 3][l_row0] = b0.w;
            Bs[0][l_kq1 * 4 + 0][l_row1] = b1.x;
            Bs[0][l_kq1 * 4 + 1][l_row1] = b1.y;
            Bs[0][l_kq1 * 4 + 2][l_row1] = b1.z;
            Bs[0][l_kq1 * 4 + 3][l_row1] = b1.w;
        }
        __syncthreads();

        for (int ks = 0; ks < NKSTEP; ++ks) {
            const int cur = ks & 1;
            const int nxt = cur ^ 1;

            // ---- issue loads for next K-step into the other stage ----
            if (ks + 1 < NKSTEP) {
                const int k0 = (ks + 1) * BK;
                float4 a0 = reinterpret_cast<const float4*>(
                                Abase + (size_t)l_row0 * E_DIM + k0)[l_kq0];
                float4 a1 = reinterpret_cast<const float4*>(
                                Abase + (size_t)l_row1 * E_DIM + k0)[l_kq1];
                int vb0 = v0 + l_row0, vb1 = v0 + l_row1;
                float4 b0 = make_float4(0.f, 0.f, 0.f, 0.f);
                float4 b1 = make_float4(0.f, 0.f, 0.f, 0.f);
                if (vb0 < V_TOTAL)
                    b0 = reinterpret_cast<const float4*>(
                             emb + (size_t)vb0 * E_DIM + k0)[l_kq0];
                if (vb1 < V_TOTAL)
                    b1 = reinterpret_cast<const float4*>(
                             emb + (size_t)vb1 * E_DIM + k0)[l_kq1];
                As[nxt][l_kq0 * 4 + 0][l_row0] = a0.x;
                As[nxt][l_kq0 * 4 + 1][l_row0] = a0.y;
                As[nxt][l_kq0 * 4 + 2][l_row0] = a0.z;
                As[nxt][l_kq0 * 4 + 3][l_row0] = a0.w;
                As[nxt][l_kq1 * 4 + 0][l_row1] = a1.x;
                As[nxt][l_kq1 * 4 + 1][l_row1] = a1.y;
                As[nxt][l_kq1 * 4 + 2][l_row1] = a1.z;
                As[nxt][l_kq1 * 4 + 3][l_row1] = a1.w;
                Bs[nxt][l_kq0 * 4 + 0][l_row0] = b0.x;
                Bs[nxt][l_kq0 * 4 + 1][l_row0] = b0.y;
                Bs[nxt][l_kq0 * 4 + 2][l_row0] = b0.z;
                Bs[nxt][l_kq0 * 4 + 3][l_row0] = b0.w;
                Bs[nxt][l_kq1 * 4 + 0][l_row1] = b1.x;
                Bs[nxt][l_kq1 * 4 + 1][l_row1] = b1.y;
                Bs[nxt][l_kq1 * 4 + 2][l_row1] = b1.z;
                Bs[nxt][l_kq1 * 4 + 3][l_row1] = b1.w;
            }

            // ---- compute current stage (GEMM + fused ||e_v||^2) ----
#pragma unroll
            for (int kk = 0; kk < BK; ++kk) {
                float4 a0 = *reinterpret_cast<const float4*>(&As[cur][kk][ty * 8]);
                float4 a1 = *reinterpret_cast<const float4*>(&As[cur][kk][ty * 8 + 4]);
                float4 b0 = *reinterpret_cast<const float4*>(&Bs[cur][kk][tx * 8]);
                float4 b1 = *reinterpret_cast<const float4*>(&Bs[cur][kk][tx * 8 + 4]);
                float ra[8] = {a0.x, a0.y, a0.z, a0.w, a1.x, a1.y, a1.z, a1.w};
                float rb[8] = {b0.x, b0.y, b0.z, b0.w, b1.x, b1.y, b1.z, b1.w};
#pragma unroll
                for (int j = 0; j < 8; ++j) {
                    bsq[j] += rb[j] * rb[j];
#pragma unroll
                    for (int i = 0; i < 8; ++i)
                        acc[i][j] += ra[i] * rb[j];
                }
            }
            __syncthreads();   // single barrier protects the stage swap
        }

        // ---- epilogue: normalize by emb norm, fold into running argmax ----
#pragma unroll
        for (int j = 0; j < 8; ++j) {
            int v = v0 + tx * 8 + j;
            if (v < V_TOTAL) {
                float inv = rsqrtf(bsq[j]);
#pragma unroll
                for (int i = 0; i < 8; ++i) {
                    float sc = acc[i][j] * inv;
                    if (sc > bestv[i]) { bestv[i] = sc; besti[i] = v; }
                }
            }
        }
    }

    // ---- cross-thread reduction over the 16 column-threads per row ----
#pragma unroll
    for (int i = 0; i < 8; ++i) {
        s_v[tid * 8 + i] = bestv[i];
        s_i[tid * 8 + i] = besti[i];
    }
    __syncthreads();

    if (tid < 128) {
        int ty2 = tid >> 3;       // row group 0..15
        int r   = tid & 7;        // row within group
        float bv = -1e30f;
        int   bi = 0x7fffffff;
        for (int txx = 0; txx < 16; ++txx) {
            int slot = (ty2 * 16 + txx) * 8 + r;
            float v = s_v[slot];
            int   i = s_i[slot];
            if (v > bv || (v == bv && i < bi)) { bv = v; bi = i; }
        }
        int token = tb * BM + ty2 * 8 + r;
        g_pval[token * VS + vs] = bv;
        g_pidx[token * VS + vs] = bi;
    }
}

// ---------------------------------------------------------------------------
// Reduce the VS partials per token (first-max tie-break == jnp.argmin
// first-occurrence semantics). Output written as FLOAT32 values: the
// comparison appears to treat the output buffer as f32 (int bit-patterns
// read back as ~0 -> rel_err exactly 1.0 in both executed rounds).
// Indices 0..49999 are exactly representable in f32.
// ---------------------------------------------------------------------------
__global__ void reduce_kernel(float* __restrict__ out, int n_out) {
    int t = blockIdx.x * blockDim.x + threadIdx.x;
    if (t >= n_out || t >= N_TOK) return;
    float bv = -1e30f;
    int   bi = 0x7fffffff;
    for (int s = 0; s < VS; ++s) {
        float v = g_pval[t * VS + s];
        int   i = g_pidx[t * VS + s];
        if (v > bv || (v == bv && i < bi)) { bv = v; bi = i; }
    }
    out[t] = (float)bi;
}

// ---------------------------------------------------------------------------
extern "C" void kernel_launch(void* const* d_in, const int* in_sizes, int n_in,
                              void* d_out, int out_size) {
    // Robust pointer assignment: identify inputs by element count, not order.
    const float* batch = nullptr;   // 2,097,152 elems
    const float* emb   = nullptr;   // 25,600,000 elems
    for (int i = 0; i < n_in; ++i) {
        if (in_sizes[i] == BATCH_ELEMS) batch = (const float*)d_in[i];
        else if (in_sizes[i] == EMB_ELEMS) emb = (const float*)d_in[i];
    }
    if (!batch) batch = (const float*)d_in[0];   // fallback to metadata order
    if (!emb)   emb   = (const float*)d_in[1];

    float* out = (float*)d_out;   // [8,512] indices, written as f32 values

    dim3 grid(VS, N_TOK / BM);                     // 9 x 32
    score_kernel<<<grid, 256>>>(batch, emb);

    reduce_kernel<<<(N_TOK + 255) / 256, 256>>>(out, out_size);
}

// round 10
// speedup vs baseline: 3.5118x; 3.5118x over previous
#include <cuda_runtime.h>
#include <cuda_bf16.h>
#include <cstdint>
#include <math.h>

// Fixed shapes: B=8,S=512,E=512,V=50000
#define V_TOTAL 50000
#define E_DIM   512
#define N_TOK   4096
#define VS      10
#define SPLIT   5000            // V_TOTAL / VS
#define NTILE   40              // ceil(SPLIT / 128)
#define CAP     64
#define MARGIN  0.10f

#define BATCH_ELEMS (N_TOK * E_DIM)     // 2097152
#define EMB_ELEMS   (V_TOTAL * E_DIM)   // 25600000

// Device-global scratch (no allocation allowed in kernel_launch)
__device__ __nv_bfloat16 g_emb_bf[EMB_ELEMS];
__device__ __nv_bfloat16 g_batch_bf[BATCH_ELEMS];
__device__ float g_inv[V_TOTAL];
__device__ int   g_cnt[N_TOK * VS];
__device__ int   g_cand[N_TOK * VS * CAP];

// Ordered-int encoding for float atomicMax (involution)
__device__ __forceinline__ int f2ord(float f) {
    int i = __float_as_int(f);
    return (i >= 0) ? i : (i ^ 0x7FFFFFFF);
}
__device__ __forceinline__ float ord2f(int k) {
    return __int_as_float((k >= 0) ? k : (k ^ 0x7FFFFFFF));
}

// cp.async helpers
__device__ __forceinline__ void cpa16(void* dst, const void* src, int bytes) {
    uint32_t d = (uint32_t)__cvta_generic_to_shared(dst);
    asm volatile("cp.async.cg.shared.global [%0], [%1], 16, %2;\n"
                 :: "r"(d), "l"(src), "r"(bytes));
}
#define CPA_COMMIT() asm volatile("cp.async.commit_group;\n")
template<int N> __device__ __forceinline__ void cpa_wait() {
    asm volatile("cp.async.wait_group %0;\n" :: "n"(N));
}

// ---------------------------------------------------------------------------
// Prep: emb -> bf16 + inv_norm (warp per row, contiguous 16 elems per lane)
// ---------------------------------------------------------------------------
__global__ void prep_emb(const float* __restrict__ emb) {
    int row  = blockIdx.x * 8 + (threadIdx.x >> 5);
    int lane = threadIdx.x & 31;
    if (row >= V_TOTAL) return;
    const float4* src = reinterpret_cast<const float4*>(emb + (size_t)row * E_DIM) + lane * 4;
    __nv_bfloat162* dst = reinterpret_cast<__nv_bfloat162*>(g_emb_bf + (size_t)row * E_DIM) + lane * 8;
    float s = 0.f;
#pragma unroll
    for (int i = 0; i < 4; ++i) {
        float4 v = src[i];
        s += v.x * v.x + v.y * v.y + v.z * v.z + v.w * v.w;
        dst[i * 2]     = __floats2bfloat162_rn(v.x, v.y);
        dst[i * 2 + 1] = __floats2bfloat162_rn(v.z, v.w);
    }
#pragma unroll
    for (int o = 16; o; o >>= 1) s += __shfl_xor_sync(0xffffffffu, s, o);
    if (lane == 0) g_inv[row] = rsqrtf(s);
}

__global__ void prep_batch(const float* __restrict__ batch) {
    int i = blockIdx.x * blockDim.x + threadIdx.x;   // one float4 per thread
    if (i * 4 >= BATCH_ELEMS) return;
    float4 v = reinterpret_cast<const float4*>(batch)[i];
    __nv_bfloat162* dst = reinterpret_cast<__nv_bfloat162*>(g_batch_bf) + i * 2;
    dst[0] = __floats2bfloat162_rn(v.x, v.y);
    dst[1] = __floats2bfloat162_rn(v.z, v.w);
}

// ---------------------------------------------------------------------------
// Stage 1: bf16 tensor-core GEMM (mma.sync m16n8k16) + split-max + candidates.
// Block = 128 tokens x one vocab split; grid (VS, 32). 256 thr = 8 warps (4Mx2N),
// warp tile 32x64, k staged in smem chunks of 32 with cp.async double buffer.
// ---------------------------------------------------------------------------
__global__ __launch_bounds__(256)
void score1() {
    __shared__ __align__(16) __nv_bfloat16 A_s[2][128][40];
    __shared__ __align__(16) __nv_bfloat16 B_s[2][128][40];
    __shared__ int   row_max[128];
    __shared__ float inv_s[128];

    const int vs   = blockIdx.x;
    const int tb   = blockIdx.y;
    const int tid  = threadIdx.x;
    const int lane = tid & 31;
    const int w    = tid >> 5;
    const int wm   = w >> 1;          // 0..3  (M warp)
    const int wn   = w & 1;           // 0..1  (N warp)
    const int g    = lane >> 2;       // groupID 0..7
    const int tg   = lane & 3;        // thread-in-group

    const int v_begin = vs * SPLIT;
    const int v_end   = v_begin + SPLIT;

    if (tid < 128) {
        row_max[tid] = 0x80000000;                    // -inf key
        g_cnt[(tb * 128 + tid) * VS + vs] = 0;        // per-launch reset (graph-safe)
    }
    __syncthreads();

    const int l_row = tid >> 1;                       // smem load row 0..127
    const int l_cj  = (tid & 1) * 2;                  // 16B chunk 0/2 (and +1)

    for (int t = 0; t < NTILE; ++t) {
        const int v0 = v_begin + t * 128;

        if (tid < 128) {
            int v = v0 + tid;
            inv_s[tid] = (v < v_end) ? g_inv[v] : 0.f;
        }

        float c[2][8][4];
#pragma unroll
        for (int mt = 0; mt < 2; ++mt)
#pragma unroll
            for (int nt = 0; nt < 8; ++nt)
#pragma unroll
                for (int q = 0; q < 4; ++q) c[mt][nt][q] = 0.f;

        // stage loader
        auto load_stage = [&](int s, int kc) {
            int k0 = kc * 32;
            const __nv_bfloat16* asrc =
                g_batch_bf + (size_t)(tb * 128 + l_row) * E_DIM + k0 + l_cj * 8;
            cpa16(&A_s[s][l_row][l_cj * 8],     asrc,     16);
            cpa16(&A_s[s][l_row][l_cj * 8 + 8], asrc + 8, 16);
            int n  = v0 + l_row;
            int nb = (n < v_end) ? 16 : 0;
            const __nv_bfloat16* bsrc =
                g_emb_bf + (size_t)min(n, V_TOTAL - 1) * E_DIM + k0 + l_cj * 8;
            cpa16(&B_s[s][l_row][l_cj * 8],     bsrc,     nb);
            cpa16(&B_s[s][l_row][l_cj * 8 + 8], bsrc + 8, nb);
        };

        load_stage(0, 0);
        CPA_COMMIT();

        for (int kc = 0; kc < 16; ++kc) {
            const int cur = kc & 1;
            if (kc + 1 < 16) {
                load_stage(cur ^ 1, kc + 1);
                CPA_COMMIT();
                cpa_wait<1>();
            } else {
                cpa_wait<0>();
            }
            __syncthreads();

#pragma unroll
            for (int ki = 0; ki < 2; ++ki) {
                const int kb = ki * 16 + tg * 2;
                uint32_t a[2][4], b[8][2];
#pragma unroll
                for (int mt = 0; mt < 2; ++mt) {
                    int r = wm * 32 + mt * 16 + g;
                    a[mt][0] = *(const uint32_t*)&A_s[cur][r][kb];
                    a[mt][1] = *(const uint32_t*)&A_s[cur][r + 8][kb];
                    a[mt][2] = *(const uint32_t*)&A_s[cur][r][kb + 8];
                    a[mt][3] = *(const uint32_t*)&A_s[cur][r + 8][kb + 8];
                }
#pragma unroll
                for (int nt = 0; nt < 8; ++nt) {
                    int n = wn * 64 + nt * 8 + g;
                    b[nt][0] = *(const uint32_t*)&B_s[cur][n][kb];
                    b[nt][1] = *(const uint32_t*)&B_s[cur][n][kb + 8];
                }
#pragma unroll
                for (int mt = 0; mt < 2; ++mt)
#pragma unroll
                    for (int nt = 0; nt < 8; ++nt)
                        asm volatile(
                            "mma.sync.aligned.m16n8k16.row.col.f32.bf16.bf16.f32 "
                            "{%0,%1,%2,%3},{%4,%5,%6,%7},{%8,%9},{%0,%1,%2,%3};\n"
                            : "+f"(c[mt][nt][0]), "+f"(c[mt][nt][1]),
                              "+f"(c[mt][nt][2]), "+f"(c[mt][nt][3])
                            : "r"(a[mt][0]), "r"(a[mt][1]), "r"(a[mt][2]), "r"(a[mt][3]),
                              "r"(b[nt][0]), "r"(b[nt][1]));
            }
            __syncthreads();
        }

        // ---- epilogue: scale + mask, split-running max, candidate insert ----
#pragma unroll
        for (int mt = 0; mt < 2; ++mt)
#pragma unroll
            for (int nt = 0; nt < 8; ++nt) {
                int nl = wn * 64 + nt * 8 + tg * 2;
#pragma unroll
                for (int q = 0; q < 4; ++q) {
                    int col = nl + (q & 1);
                    int v   = v0 + col;
                    c[mt][nt][q] = (v < v_end) ? c[mt][nt][q] * inv_s[col] : -1e30f;
                }
            }

        float rmax[4] = {-1e30f, -1e30f, -1e30f, -1e30f};   // rows g,g+8,g+16,g+24 (+wm*32)
#pragma unroll
        for (int mt = 0; mt < 2; ++mt)
#pragma unroll
            for (int nt = 0; nt < 8; ++nt)
#pragma unroll
                for (int q = 0; q < 4; ++q) {
                    int ri = mt * 2 + (q >> 1);
                    rmax[ri] = fmaxf(rmax[ri], c[mt][nt][q]);
                }
#pragma unroll
        for (int ri = 0; ri < 4; ++ri) {
            int r = wm * 32 + (ri >> 1) * 16 + g + (ri & 1) * 8;
            atomicMax(&row_max[r], f2ord(rmax[ri]));
        }
        __syncthreads();

        float thr[4];
#pragma unroll
        for (int ri = 0; ri < 4; ++ri) {
            int r = wm * 32 + (ri >> 1) * 16 + g + (ri & 1) * 8;
            thr[ri] = ord2f(row_max[r]) - MARGIN;
        }
#pragma unroll
        for (int mt = 0; mt < 2; ++mt)
#pragma unroll
            for (int nt = 0; nt < 8; ++nt)
#pragma unroll
                for (int q = 0; q < 4; ++q) {
                    int ri = mt * 2 + (q >> 1);
                    float s = c[mt][nt][q];
                    if (s > thr[ri]) {
                        int col   = wn * 64 + nt * 8 + tg * 2 + (q & 1);
                        int v     = v0 + col;
                        int token = tb * 128 + wm * 32 + (ri >> 1) * 16 + g + (ri & 1) * 8;
                        int slot  = atomicAdd(&g_cnt[token * VS + vs], 1);
                        if (slot < CAP) g_cand[(token * VS + vs) * CAP + slot] = v;
                    }
                }
        __syncthreads();   // protect smem reuse by next tile
    }
}

// ---------------------------------------------------------------------------
// Stage 2: exact fp32 rescore of candidates; warp per token; lowest-index
// tie-break == jnp.argmin first-occurrence.
// ---------------------------------------------------------------------------
__global__ void rescore(const float* __restrict__ batch, const float* __restrict__ emb,
                        float* __restrict__ out) {
    int warp = (blockIdx.x * blockDim.x + threadIdx.x) >> 5;
    int lane = threadIdx.x & 31;
    if (warp >= N_TOK) return;
    const int t = warp;

    float bb[16];
#pragma unroll
    for (int j = 0; j < 16; ++j) bb[j] = batch[(size_t)t * E_DIM + lane + 32 * j];

    float bestv = -1e30f;
    int   besti = 0x7fffffff;
    for (int vs = 0; vs < VS; ++vs) {
        int c = g_cnt[t * VS + vs];
        if (c > CAP) c = CAP;
        for (int i = 0; i < c; ++i) {
            int v = g_cand[(t * VS + vs) * CAP + i];
            const float* e = emb + (size_t)v * E_DIM;
            float s = 0.f;
#pragma unroll
            for (int j = 0; j < 16; ++j) s += bb[j] * e[lane + 32 * j];
#pragma unroll
            for (int o = 16; o; o >>= 1) s += __shfl_xor_sync(0xffffffffu, s, o);
            s *= g_inv[v];
            if (s > bestv || (s == bestv && v < besti)) { bestv = s; besti = v; }
        }
    }
    if (lane == 0) out[t] = (float)besti;
}

// ---------------------------------------------------------------------------
extern "C" void kernel_launch(void* const* d_in, const int* in_sizes, int n_in,
                              void* d_out, int out_size) {
    const float* batch = nullptr;
    const float* emb   = nullptr;
    for (int i = 0; i < n_in; ++i) {
        if (in_sizes[i] == BATCH_ELEMS)    batch = (const float*)d_in[i];
        else if (in_sizes[i] == EMB_ELEMS) emb   = (const float*)d_in[i];
    }
    if (!batch) batch = (const float*)d_in[0];
    if (!emb)   emb   = (const float*)d_in[1];

    float* out = (float*)d_out;   // [8,512] indices written as f32 values

    prep_emb<<<(V_TOTAL + 7) / 8, 256>>>(emb);
    prep_batch<<<(BATCH_ELEMS / 4 + 255) / 256, 256>>>(batch);

    dim3 grid(VS, N_TOK / 128);   // 10 x 32
    score1<<<grid, 256>>>();

    rescore<<<(N_TOK * 32 + 255) / 256, 256>>>(batch, emb, out);
}

// round 12
// speedup vs baseline: 3.6781x; 1.0474x over previous
#include <cuda_runtime.h>
#include <cuda_bf16.h>
#include <cstdint>
#include <math.h>

// Fixed shapes: B=8,S=512,E=512,V=50000
#define V_TOTAL 50000
#define E_DIM   512
#define N_TOK   4096
#define VS      10
#define SPLIT   5000            // V_TOTAL / VS
#define NTILE   40              // SPLIT / 128 (with tail guard)
#define CAP     64
#define MARGIN  0.10f

#define BK      32
#define NKC     (E_DIM / BK)    // 16 k-chunks
#define NSTAGE  4
#define PADK    40              // row stride (bank-conflict-free, proven)

#define BATCH_ELEMS (N_TOK * E_DIM)     // 2097152
#define EMB_ELEMS   (V_TOTAL * E_DIM)   // 25600000

#define STAGE_BYTES (128 * PADK * 2)            // 10240 per array per stage
#define DSMEM_BYTES (2 * NSTAGE * STAGE_BYTES)  // 81920

// Device-global scratch (no allocation allowed in kernel_launch)
__device__ __nv_bfloat16 g_emb_bf[EMB_ELEMS];
__device__ __nv_bfloat16 g_batch_bf[BATCH_ELEMS];
__device__ float g_inv[V_TOTAL];
__device__ int   g_cnt[N_TOK * VS];
__device__ int   g_cand[N_TOK * VS * CAP];

// Ordered-int encoding for float atomicMax (involution)
__device__ __forceinline__ int f2ord(float f) {
    int i = __float_as_int(f);
    return (i >= 0) ? i : (i ^ 0x7FFFFFFF);
}
__device__ __forceinline__ float ord2f(int k) {
    return __int_as_float((k >= 0) ? k : (k ^ 0x7FFFFFFF));
}

// cp.async helpers
__device__ __forceinline__ void cpa16(void* dst, const void* src, int bytes) {
    uint32_t d = (uint32_t)__cvta_generic_to_shared(dst);
    asm volatile("cp.async.cg.shared.global [%0], [%1], 16, %2;\n"
                 :: "r"(d), "l"(src), "r"(bytes));
}
#define CPA_COMMIT() asm volatile("cp.async.commit_group;\n")
template<int N> __device__ __forceinline__ void cpa_wait() {
    asm volatile("cp.async.wait_group %0;\n" :: "n"(N));
}

__device__ __forceinline__ void ldsm_x4(uint32_t& r0, uint32_t& r1,
                                        uint32_t& r2, uint32_t& r3, const void* p) {
    uint32_t a = (uint32_t)__cvta_generic_to_shared(p);
    asm volatile("ldmatrix.sync.aligned.m8n8.x4.shared.b16 {%0,%1,%2,%3}, [%4];"
                 : "=r"(r0), "=r"(r1), "=r"(r2), "=r"(r3) : "r"(a));
}

// ---------------------------------------------------------------------------
// Prep: emb -> bf16 + inv_norm; batch -> bf16
// ---------------------------------------------------------------------------
__global__ void prep_emb(const float* __restrict__ emb) {
    int row  = blockIdx.x * 8 + (threadIdx.x >> 5);
    int lane = threadIdx.x & 31;
    if (row >= V_TOTAL) return;
    const float4* src = reinterpret_cast<const float4*>(emb + (size_t)row * E_DIM) + lane * 4;
    __nv_bfloat162* dst = reinterpret_cast<__nv_bfloat162*>(g_emb_bf + (size_t)row * E_DIM) + lane * 8;
    float s = 0.f;
#pragma unroll
    for (int i = 0; i < 4; ++i) {
        float4 v = src[i];
        s += v.x * v.x + v.y * v.y + v.z * v.z + v.w * v.w;
        dst[i * 2]     = __floats2bfloat162_rn(v.x, v.y);
        dst[i * 2 + 1] = __floats2bfloat162_rn(v.z, v.w);
    }
#pragma unroll
    for (int o = 16; o; o >>= 1) s += __shfl_xor_sync(0xffffffffu, s, o);
    if (lane == 0) g_inv[row] = rsqrtf(s);
}

__global__ void prep_batch(const float* __restrict__ batch) {
    int i = blockIdx.x * blockDim.x + threadIdx.x;
    if (i * 4 >= BATCH_ELEMS) return;
    float4 v = reinterpret_cast<const float4*>(batch)[i];
    __nv_bfloat162* dst = reinterpret_cast<__nv_bfloat162*>(g_batch_bf) + i * 2;
    dst[0] = __floats2bfloat162_rn(v.x, v.y);
    dst[1] = __floats2bfloat162_rn(v.z, v.w);
}

// ---------------------------------------------------------------------------
// Stage 1: bf16 mma.sync GEMM + split-max + candidate capture.
// 4-stage cp.async pipeline (BK=32), ldmatrix fragment loads.
// Block: 128 tokens x one vocab split; 256 thr = 8 warps (4M x 2N), warp 32x64.
// ---------------------------------------------------------------------------
__global__ __launch_bounds__(256)
void score1() {
    extern __shared__ __align__(16) char dsm[];
    typedef __nv_bfloat16 (*Tile)[128][PADK];
    Tile A_s = reinterpret_cast<Tile>(dsm);                              // [4][128][40]
    Tile B_s = reinterpret_cast<Tile>(dsm + NSTAGE * STAGE_BYTES);       // [4][128][40]

    __shared__ int   row_max[128];
    __shared__ float inv_s[128];

    const int vs   = blockIdx.x;
    const int tb   = blockIdx.y;
    const int tid  = threadIdx.x;
    const int lane = tid & 31;
    const int w    = tid >> 5;
    const int wm   = w >> 1;          // 0..3 (M warp)
    const int wn   = w & 1;           // 0..1 (N warp)
    const int g    = lane >> 2;       // 0..7
    const int tg   = lane & 3;        // 0..3

    // ldmatrix lane addressing (same formula for A and B fragments)
    const int lr = (lane & 7) + ((lane >> 3) & 1) * 8;  // row within 16
    const int lc = ((lane >> 4) & 1) * 8;               // k offset 0/8

    const int v_begin = vs * SPLIT;
    const int v_end   = v_begin + SPLIT;

    if (tid < 128) {
        row_max[tid] = 0x80000000;
        g_cnt[(tb * 128 + tid) * VS + vs] = 0;   // per-launch reset (graph-safe)
    }
    __syncthreads();

    // loader coords: 2 x 16B chunks per thread per array (512 chunks total)
    const int l_row0 = (tid * 2)     >> 2, l_q0 = (tid * 2)     & 3;
    const int l_row1 = (tid * 2 + 1) >> 2, l_q1 = (tid * 2 + 1) & 3;

    for (int t = 0; t < NTILE; ++t) {
        const int v0 = v_begin + t * 128;

        if (tid < 128) {
            int v = v0 + tid;
            inv_s[tid] = (v < v_end) ? g_inv[v] : 0.f;
        }

        float c[2][8][4];
#pragma unroll
        for (int mt = 0; mt < 2; ++mt)
#pragma unroll
            for (int nt = 0; nt < 8; ++nt)
#pragma unroll
                for (int q = 0; q < 4; ++q) c[mt][nt][q] = 0.f;

        auto load_stage = [&](int s, int kc) {
            int k0 = kc * BK;
            cpa16(&A_s[s][l_row0][l_q0 * 8],
                  g_batch_bf + (size_t)(tb * 128 + l_row0) * E_DIM + k0 + l_q0 * 8, 16);
            cpa16(&A_s[s][l_row1][l_q1 * 8],
                  g_batch_bf + (size_t)(tb * 128 + l_row1) * E_DIM + k0 + l_q1 * 8, 16);
            int n0 = v0 + l_row0, n1 = v0 + l_row1;
            cpa16(&B_s[s][l_row0][l_q0 * 8],
                  g_emb_bf + (size_t)min(n0, V_TOTAL - 1) * E_DIM + k0 + l_q0 * 8,
                  (n0 < v_end) ? 16 : 0);
            cpa16(&B_s[s][l_row1][l_q1 * 8],
                  g_emb_bf + (size_t)min(n1, V_TOTAL - 1) * E_DIM + k0 + l_q1 * 8,
                  (n1 < v_end) ? 16 : 0);
        };

        // prologue: fill 3 stages
#pragma unroll
        for (int p = 0; p < NSTAGE - 1; ++p) { load_stage(p, p); CPA_COMMIT(); }

        for (int kc = 0; kc < NKC; ++kc) {
            const int cur = kc & (NSTAGE - 1);

            if (kc < NKC - 2)      cpa_wait<2>();
            else if (kc == NKC - 2) cpa_wait<1>();
            else                    cpa_wait<0>();
            __syncthreads();

#pragma unroll
            for (int ki = 0; ki < 2; ++ki) {
                const int kb = ki * 16;
                uint32_t a[2][4], b[8][2];
#pragma unroll
                for (int mt = 0; mt < 2; ++mt)
                    ldsm_x4(a[mt][0], a[mt][1], a[mt][2], a[mt][3],
                            &A_s[cur][wm * 32 + mt * 16 + lr][kb + lc]);
#pragma unroll
                for (int ntp = 0; ntp < 4; ++ntp) {
                    uint32_t m0, m1, m2, m3;
                    ldsm_x4(m0, m1, m2, m3,
                            &B_s[cur][wn * 64 + ntp * 16 + lr][kb + lc]);
                    b[ntp * 2][0]     = m0;  b[ntp * 2 + 1][0] = m1;
                    b[ntp * 2][1]     = m2;  b[ntp * 2 + 1][1] = m3;
                }
#pragma unroll
                for (int mt = 0; mt < 2; ++mt)
#pragma unroll
                    for (int nt = 0; nt < 8; ++nt)
                        asm volatile(
                            "mma.sync.aligned.m16n8k16.row.col.f32.bf16.bf16.f32 "
                            "{%0,%1,%2,%3},{%4,%5,%6,%7},{%8,%9},{%0,%1,%2,%3};\n"
                            : "+f"(c[mt][nt][0]), "+f"(c[mt][nt][1]),
                              "+f"(c[mt][nt][2]), "+f"(c[mt][nt][3])
                            : "r"(a[mt][0]), "r"(a[mt][1]), "r"(a[mt][2]), "r"(a[mt][3]),
                              "r"(b[nt][0]), "r"(b[nt][1]));
            }

            if (kc + NSTAGE - 1 < NKC) { load_stage((kc + NSTAGE - 1) & (NSTAGE - 1), kc + NSTAGE - 1); CPA_COMMIT(); }
        }

        // ---- epilogue: scale + mask, split-running max, candidate insert ----
#pragma unroll
        for (int mt = 0; mt < 2; ++mt)
#pragma unroll
            for (int nt = 0; nt < 8; ++nt) {
                int nl = wn * 64 + nt * 8 + tg * 2;
#pragma unroll
                for (int q = 0; q < 4; ++q) {
                    int col = nl + (q & 1);
                    int v   = v0 + col;
                    c[mt][nt][q] = (v < v_end) ? c[mt][nt][q] * inv_s[col] : -1e30f;
                }
            }

        float rmax[4] = {-1e30f, -1e30f, -1e30f, -1e30f};
#pragma unroll
        for (int mt = 0; mt < 2; ++mt)
#pragma unroll
            for (int nt = 0; nt < 8; ++nt)
#pragma unroll
                for (int q = 0; q < 4; ++q) {
                    int ri = mt * 2 + (q >> 1);
                    rmax[ri] = fmaxf(rmax[ri], c[mt][nt][q]);
                }
#pragma unroll
        for (int ri = 0; ri < 4; ++ri) {
            int r = wm * 32 + (ri >> 1) * 16 + g + (ri & 1) * 8;
            atomicMax(&row_max[r], f2ord(rmax[ri]));
        }
        __syncthreads();

        float thr[4];
#pragma unroll
        for (int ri = 0; ri < 4; ++ri) {
            int r = wm * 32 + (ri >> 1) * 16 + g + (ri & 1) * 8;
            thr[ri] = ord2f(row_max[r]) - MARGIN;
        }
#pragma unroll
        for (int mt = 0; mt < 2; ++mt)
#pragma unroll
            for (int nt = 0; nt < 8; ++nt)
#pragma unroll
                for (int q = 0; q < 4; ++q) {
                    int ri = mt * 2 + (q >> 1);
                    float s = c[mt][nt][q];
                    if (s > thr[ri]) {
                        int col   = wn * 64 + nt * 8 + tg * 2 + (q & 1);
                        int v     = v0 + col;
                        int token = tb * 128 + wm * 32 + (ri >> 1) * 16 + g + (ri & 1) * 8;
                        int slot  = atomicAdd(&g_cnt[token * VS + vs], 1);
                        if (slot < CAP) g_cand[(token * VS + vs) * CAP + slot] = v;
                    }
                }
        __syncthreads();   // protect inv_s/smem reuse by next tile
    }
}

// ---------------------------------------------------------------------------
// Stage 2: exact fp32 rescore; warp per token; lowest-index tie-break.
// ---------------------------------------------------------------------------
__global__ void rescore(const float* __restrict__ batch, const float* __restrict__ emb,
                        float* __restrict__ out) {
    int warp = (blockIdx.x * blockDim.x + threadIdx.x) >> 5;
    int lane = threadIdx.x & 31;
    if (warp >= N_TOK) return;
    const int t = warp;

    float bb[16];
#pragma unroll
    for (int j = 0; j < 16; ++j) bb[j] = batch[(size_t)t * E_DIM + lane + 32 * j];

    float bestv = -1e30f;
    int   besti = 0x7fffffff;
    for (int vs = 0; vs < VS; ++vs) {
        int c = g_cnt[t * VS + vs];
        if (c > CAP) c = CAP;
        for (int i = 0; i < c; ++i) {
            int v = g_cand[(t * VS + vs) * CAP + i];
            const float* e = emb + (size_t)v * E_DIM;
            float s = 0.f;
#pragma unroll
            for (int j = 0; j < 16; ++j) s += bb[j] * e[lane + 32 * j];
#pragma unroll
            for (int o = 16; o; o >>= 1) s += __shfl_xor_sync(0xffffffffu, s, o);
            s *= g_inv[v];
            if (s > bestv || (s == bestv && v < besti)) { bestv = s; besti = v; }
        }
    }
    if (lane == 0) out[t] = (float)besti;
}

// ---------------------------------------------------------------------------
extern "C" void kernel_launch(void* const* d_in, const int* in_sizes, int n_in,
                              void* d_out, int out_size) {
    const float* batch = nullptr;
    const float* emb   = nullptr;
    for (int i = 0; i < n_in; ++i) {
        if (in_sizes[i] == BATCH_ELEMS)    batch = (const float*)d_in[i];
        else if (in_sizes[i] == EMB_ELEMS) emb   = (const float*)d_in[i];
    }
    if (!batch) batch = (const float*)d_in[0];
    if (!emb)   emb   = (const float*)d_in[1];

    float* out = (float*)d_out;   // [8,512] indices written as f32 values

    cudaFuncSetAttribute(score1, cudaFuncAttributeMaxDynamicSharedMemorySize, DSMEM_BYTES);

    prep_emb<<<(V_TOTAL + 7) / 8, 256>>>(emb);
    prep_batch<<<(BATCH_ELEMS / 4 + 255) / 256, 256>>>(batch);

    dim3 grid(VS, N_TOK / 128);   // 10 x 32
    score1<<<grid, 256, DSMEM_BYTES>>>();

    rescore<<<(N_TOK * 32 + 255) / 256, 256>>>(batch, emb, out);
}

// round 15
// speedup vs baseline: 3.7764x; 1.0267x over previous
#include <cuda_runtime.h>
#include <cuda_fp16.h>
#include <cstdint>
#include <math.h>

// Fixed shapes: B=8,S=512,E=512,V=50000
#define V_TOTAL 50000
#define E_DIM   512
#define N_TOK   4096
#define VS      10
#define SPLIT   5000            // V_TOTAL / VS
#define NTILE   40              // SPLIT / 128
#define CAP     64
#define MARGIN  0.10f

#define BK      32
#define NKC     (E_DIM / BK)    // 16 k-chunks
#define NSTAGE  4
#define PADK    40              // row stride (bank-conflict-free, proven)

#define BATCH_ELEMS (N_TOK * E_DIM)     // 2097152
#define EMB_ELEMS   (V_TOTAL * E_DIM)   // 25600000

#define STAGE_BYTES (128 * PADK * 2)            // 10240 per array per stage
#define DSMEM_BYTES (2 * NSTAGE * STAGE_BYTES)  // 81920

// Device-global scratch (no allocation allowed in kernel_launch)
__device__ __half g_emb_h[EMB_ELEMS];
__device__ __half g_batch_h[BATCH_ELEMS];
__device__ float g_inv[V_TOTAL];
__device__ int   g_cnt[N_TOK * VS];
__device__ int   g_cand[N_TOK * VS * CAP];

// cp.async helpers
__device__ __forceinline__ void cpa16(void* dst, const void* src, int bytes) {
    uint32_t d = (uint32_t)__cvta_generic_to_shared(dst);
    asm volatile("cp.async.cg.shared.global [%0], [%1], 16, %2;\n"
                 :: "r"(d), "l"(src), "r"(bytes));
}
#define CPA_COMMIT() asm volatile("cp.async.commit_group;\n")
template<int N> __device__ __forceinline__ void cpa_wait() {
    asm volatile("cp.async.wait_group %0;\n" :: "n"(N));
}

__device__ __forceinline__ void ldsm_x4(uint32_t& r0, uint32_t& r1,
                                        uint32_t& r2, uint32_t& r3, const void* p) {
    uint32_t a = (uint32_t)__cvta_generic_to_shared(p);
    asm volatile("ldmatrix.sync.aligned.m8n8.x4.shared.b16 {%0,%1,%2,%3}, [%4];"
                 : "=r"(r0), "=r"(r1), "=r"(r2), "=r"(r3) : "r"(a));
}

// ---------------------------------------------------------------------------
// Prep: emb -> fp16 + inv_norm; batch -> fp16
// ---------------------------------------------------------------------------
__global__ void prep_emb(const float* __restrict__ emb) {
    int row  = blockIdx.x * 8 + (threadIdx.x >> 5);
    int lane = threadIdx.x & 31;
    if (row >= V_TOTAL) return;
    const float4* src = reinterpret_cast<const float4*>(emb + (size_t)row * E_DIM) + lane * 4;
    __half2* dst = reinterpret_cast<__half2*>(g_emb_h + (size_t)row * E_DIM) + lane * 8;
    float s = 0.f;
#pragma unroll
    for (int i = 0; i < 4; ++i) {
        float4 v = src[i];
        s += v.x * v.x + v.y * v.y + v.z * v.z + v.w * v.w;
        dst[i * 2]     = __floats2half2_rn(v.x, v.y);
        dst[i * 2 + 1] = __floats2half2_rn(v.z, v.w);
    }
#pragma unroll
    for (int o = 16; o; o >>= 1) s += __shfl_xor_sync(0xffffffffu, s, o);
    if (lane == 0) g_inv[row] = rsqrtf(s);
}

__global__ void prep_batch(const float* __restrict__ batch) {
    int i = blockIdx.x * blockDim.x + threadIdx.x;
    if (i * 4 >= BATCH_ELEMS) return;
    float4 v = reinterpret_cast<const float4*>(batch)[i];
    __half2* dst = reinterpret_cast<__half2*>(g_batch_h) + i * 2;
    dst[0] = __floats2half2_rn(v.x, v.y);
    dst[1] = __floats2half2_rn(v.z, v.w);
}

// ---------------------------------------------------------------------------
// Stage 1: fp16 mma.sync (f16 accumulators, 2x HMMA rate) + split-max +
// candidate capture. 4-stage cp.async (BK=32), ldmatrix fragment loads.
// Block: 128 tokens x one vocab split; 256 thr = 8 warps (4M x 2N), warp 32x64.
// ---------------------------------------------------------------------------
__global__ __launch_bounds__(256)
void score1() {
    extern __shared__ __align__(16) char dsm[];
    typedef __half (*Tile)[128][PADK];
    Tile A_s = reinterpret_cast<Tile>(dsm);                              // [4][128][40]
    Tile B_s = reinterpret_cast<Tile>(dsm + NSTAGE * STAGE_BYTES);       // [4][128][40]

    __shared__ int   row_max[128];
    __shared__ float inv_s[128];

    const int vs   = blockIdx.x;
    const int tb   = blockIdx.y;
    const int tid  = threadIdx.x;
    const int lane = tid & 31;
    const int w    = tid >> 5;
    const int wm   = w >> 1;          // 0..3 (M warp)
    const int wn   = w & 1;           // 0..1 (N warp)
    const int g    = lane >> 2;       // 0..7
    const int tg   = lane & 3;        // 0..3

    const int lr = (lane & 7) + ((lane >> 3) & 1) * 8;  // ldmatrix row in 16
    const int lc = ((lane >> 4) & 1) * 8;               // k offset 0/8

    const int v_begin = vs * SPLIT;
    const int v_end   = v_begin + SPLIT;

    if (tid < 128) {
        row_max[tid] = 0x80000000;
        g_cnt[(tb * 128 + tid) * VS + vs] = 0;   // per-launch reset (graph-safe)
    }
    __syncthreads();

    const int l_row0 = (tid * 2)     >> 2, l_q0 = (tid * 2)     & 3;
    const int l_row1 = (tid * 2 + 1) >> 2, l_q1 = (tid * 2 + 1) & 3;

    for (int t = 0; t < NTILE; ++t) {
        const int v0 = v_begin + t * 128;

        if (tid < 128) {
            int v = v0 + tid;
            inv_s[tid] = (v < v_end) ? g_inv[v] : 0.f;
        }

        // f16-accumulator pairs: c[mt][nt][0] = {row g, cols 2tg,2tg+1},
        //                        c[mt][nt][1] = {row g+8, same cols}
        uint32_t c[2][8][2];
#pragma unroll
        for (int mt = 0; mt < 2; ++mt)
#pragma unroll
            for (int nt = 0; nt < 8; ++nt) { c[mt][nt][0] = 0u; c[mt][nt][1] = 0u; }

        auto load_stage = [&](int s, int kc) {
            int k0 = kc * BK;
            cpa16(&A_s[s][l_row0][l_q0 * 8],
                  g_batch_h + (size_t)(tb * 128 + l_row0) * E_DIM + k0 + l_q0 * 8, 16);
            cpa16(&A_s[s][l_row1][l_q1 * 8],
                  g_batch_h + (size_t)(tb * 128 + l_row1) * E_DIM + k0 + l_q1 * 8, 16);
            int n0 = v0 + l_row0, n1 = v0 + l_row1;
            cpa16(&B_s[s][l_row0][l_q0 * 8],
                  g_emb_h + (size_t)min(n0, V_TOTAL - 1) * E_DIM + k0 + l_q0 * 8,
                  (n0 < v_end) ? 16 : 0);
            cpa16(&B_s[s][l_row1][l_q1 * 8],
                  g_emb_h + (size_t)min(n1, V_TOTAL - 1) * E_DIM + k0 + l_q1 * 8,
                  (n1 < v_end) ? 16 : 0);
        };

        // prologue: fill 3 stages
#pragma unroll
        for (int p = 0; p < NSTAGE - 1; ++p) { load_stage(p, p); CPA_COMMIT(); }

        for (int kc = 0; kc < NKC; ++kc) {
            const int cur = kc & (NSTAGE - 1);

            if (kc < NKC - 2)       cpa_wait<2>();
            else if (kc == NKC - 2) cpa_wait<1>();
            else                    cpa_wait<0>();
            __syncthreads();

#pragma unroll
            for (int ki = 0; ki < 2; ++ki) {
                const int kb = ki * 16;
                uint32_t a[2][4], b[8][2];
#pragma unroll
                for (int mt = 0; mt < 2; ++mt)
                    ldsm_x4(a[mt][0], a[mt][1], a[mt][2], a[mt][3],
                            &A_s[cur][wm * 32 + mt * 16 + lr][kb + lc]);
#pragma unroll
                for (int ntp = 0; ntp < 4; ++ntp) {
                    uint32_t m0, m1, m2, m3;
                    ldsm_x4(m0, m1, m2, m3,
                            &B_s[cur][wn * 64 + ntp * 16 + lr][kb + lc]);
                    b[ntp * 2][0]     = m0;  b[ntp * 2 + 1][0] = m1;
                    b[ntp * 2][1]     = m2;  b[ntp * 2 + 1][1] = m3;
                }
#pragma unroll
                for (int mt = 0; mt < 2; ++mt)
#pragma unroll
                    for (int nt = 0; nt < 8; ++nt)
                        asm volatile(
                            "mma.sync.aligned.m16n8k16.row.col.f16.f16.f16.f16 "
                            "{%0,%1},{%2,%3,%4,%5},{%6,%7},{%0,%1};\n"
                            : "+r"(c[mt][nt][0]), "+r"(c[mt][nt][1])
                            : "r"(a[mt][0]), "r"(a[mt][1]), "r"(a[mt][2]), "r"(a[mt][3]),
                              "r"(b[nt][0]), "r"(b[nt][1]));
            }

            if (kc + NSTAGE - 1 < NKC) {
                load_stage((kc + NSTAGE - 1) & (NSTAGE - 1), kc + NSTAGE - 1);
                CPA_COMMIT();
            }
        }

        // ---- epilogue: unpack f16 pairs -> f32, scale+mask, split max,
        //      candidate insert (identical logic to validated R12) ----
        float cf[2][8][4];
#pragma unroll
        for (int mt = 0; mt < 2; ++mt)
#pragma unroll
            for (int nt = 0; nt < 8; ++nt) {
                __half2 h0 = *reinterpret_cast<__half2*>(&c[mt][nt][0]);
                __half2 h1 = *reinterpret_cast<__half2*>(&c[mt][nt][1]);
                cf[mt][nt][0] = __low2float(h0);
                cf[mt][nt][1] = __high2float(h0);
                cf[mt][nt][2] = __low2float(h1);
                cf[mt][nt][3] = __high2float(h1);
                int nl = wn * 64 + nt * 8 + tg * 2;
#pragma unroll
                for (int q = 0; q < 4; ++q) {
                    int col = nl + (q & 1);
                    int v   = v0 + col;
                    cf[mt][nt][q] = (v < v_end) ? cf[mt][nt][q] * inv_s[col] : -1e30f;
                }
            }

        float rmax[4] = {-1e30f, -1e30f, -1e30f, -1e30f};
#pragma unroll
        for (int mt = 0; mt < 2; ++mt)
#pragma unroll
            for (int nt = 0; nt < 8; ++nt)
#pragma unroll
                for (int q = 0; q < 4; ++q) {
                    int ri = mt * 2 + (q >> 1);
                    rmax[ri] = fmaxf(rmax[ri], cf[mt][nt][q]);
                }
        // ordered-int shared atomicMax
#pragma unroll
        for (int ri = 0; ri < 4; ++ri) {
            int r = wm * 32 + (ri >> 1) * 16 + g + (ri & 1) * 8;
            int key = __float_as_int(rmax[ri]);
            key = (key >= 0) ? key : (key ^ 0x7FFFFFFF);
            atomicMax(&row_max[r], key);
        }
        __syncthreads();

        float thr[4];
#pragma unroll
        for (int ri = 0; ri < 4; ++ri) {
            int r = wm * 32 + (ri >> 1) * 16 + g + (ri & 1) * 8;
            int key = row_max[r];
            float m = __int_as_float((key >= 0) ? key : (key ^ 0x7FFFFFFF));
            thr[ri] = m - MARGIN;
        }
#pragma unroll
        for (int mt = 0; mt < 2; ++mt)
#pragma unroll
            for (int nt = 0; nt < 8; ++nt)
#pragma unroll
                for (int q = 0; q < 4; ++q) {
                    int ri = mt * 2 + (q >> 1);
                    float s = cf[mt][nt][q];
                    if (s > thr[ri]) {
                        int col   = wn * 64 + nt * 8 + tg * 2 + (q & 1);
                        int v     = v0 + col;
                        int token = tb * 128 + wm * 32 + (ri >> 1) * 16 + g + (ri & 1) * 8;
                        int slot  = atomicAdd(&g_cnt[token * VS + vs], 1);
                        if (slot < CAP) g_cand[(token * VS + vs) * CAP + slot] = v;
                    }
                }
        __syncthreads();   // protect inv_s/smem reuse by next tile
    }
}

// ---------------------------------------------------------------------------
// Stage 2: exact fp32 rescore; warp per token; lowest-index tie-break.
// ---------------------------------------------------------------------------
__global__ void rescore(const float* __restrict__ batch, const float* __restrict__ emb,
                        float* __restrict__ out) {
    int warp = (blockIdx.x * blockDim.x + threadIdx.x) >> 5;
    int lane = threadIdx.x & 31;
    if (warp >= N_TOK) return;
    const int t = warp;

    float bb[16];
#pragma unroll
    for (int j = 0; j < 16; ++j) bb[j] = batch[(size_t)t * E_DIM + lane + 32 * j];

    float bestv = -1e30f;
    int   besti = 0x7fffffff;
    for (int vs = 0; vs < VS; ++vs) {
        int c = g_cnt[t * VS + vs];
        if (c > CAP) c = CAP;
        for (int i = 0; i < c; ++i) {
            int v = g_cand[(t * VS + vs) * CAP + i];
            const float* e = emb + (size_t)v * E_DIM;
            float s = 0.f;
#pragma unroll
            for (int j = 0; j < 16; ++j) s += bb[j] * e[lane + 32 * j];
#pragma unroll
            for (int o = 16; o; o >>= 1) s += __shfl_xor_sync(0xffffffffu, s, o);
            s *= g_inv[v];
            if (s > bestv || (s == bestv && v < besti)) { bestv = s; besti = v; }
        }
    }
    if (lane == 0) out[t] = (float)besti;
}

// ---------------------------------------------------------------------------
extern "C" void kernel_launch(void* const* d_in, const int* in_sizes, int n_in,
                              void* d_out, int out_size) {
    const float* batch = nullptr;
    const float* emb   = nullptr;
    for (int i = 0; i < n_in; ++i) {
        if (in_sizes[i] == BATCH_ELEMS)    batch = (const float*)d_in[i];
        else if (in_sizes[i] == EMB_ELEMS) emb   = (const float*)d_in[i];
    }
    if (!batch) batch = (const float*)d_in[0];
    if (!emb)   emb   = (const float*)d_in[1];

    float* out = (float*)d_out;   // [8,512] indices written as f32 values

    cudaFuncSetAttribute(score1, cudaFuncAttributeMaxDynamicSharedMemorySize, DSMEM_BYTES);

    prep_emb<<<(V_TOTAL + 7) / 8, 256>>>(emb);
    prep_batch<<<(BATCH_ELEMS / 4 + 255) / 256, 256>>>(batch);

    dim3 grid(VS, N_TOK / 128);   // 10 x 32
    score1<<<grid, 256, DSMEM_BYTES>>>();

    rescore<<<(N_TOK * 32 + 255) / 256, 256>>>(batch, emb, out);
}

// round 17
// speedup vs baseline: 9.3996x; 2.4890x over previous
#include <cuda_runtime.h>
#include <cuda_fp16.h>
#include <cstdint>
#include <math.h>

// Fixed shapes: B=8,S=512,E=512,V=50000
#define V_TOTAL 50000
#define E_DIM   512
#define N_TOK   4096
#define VS      9
#define SPLIT   5556            // ceil(V/VS)
#define CAP     64
#define MARGIN  0.10f

#define NKC     8               // k-chunks of 64 bytes (s8) per tile
#define NSTAGE  4
#define PADB    80              // row stride bytes (bank-conflict-free, proven at 80B)

#define BATCH_ELEMS (N_TOK * E_DIM)     // 2097152
#define EMB_ELEMS   (V_TOTAL * E_DIM)   // 25600000

#define STAGE_BYTES (128 * PADB)                // 10240 per array per stage
#define DSMEM_BYTES (2 * NSTAGE * STAGE_BYTES)  // 81920

// Device-global scratch
__device__ __align__(16) int8_t g_emb_q[EMB_ELEMS];    // quantized normalized emb
__device__ __align__(16) int8_t g_batch_q[BATCH_ELEMS];
__device__ float g_es[V_TOTAL];    // per-emb-row dequant scale (max|e_hat|/127)
__device__ float g_bs[N_TOK];      // per-token dequant scale (max|b|/127)
__device__ float g_inv[V_TOTAL];   // exact fp32 1/||e|| for rescore
__device__ int   g_cnt[N_TOK * VS];
__device__ int   g_cand[N_TOK * VS * CAP];

// cp.async helpers
__device__ __forceinline__ void cpa16(void* dst, const void* src, int bytes) {
    uint32_t d = (uint32_t)__cvta_generic_to_shared(dst);
    asm volatile("cp.async.cg.shared.global [%0], [%1], 16, %2;\n"
                 :: "r"(d), "l"(src), "r"(bytes));
}
#define CPA_COMMIT() asm volatile("cp.async.commit_group;\n")
template<int N> __device__ __forceinline__ void cpa_wait() {
    asm volatile("cp.async.wait_group %0;\n" :: "n"(N));
}

__device__ __forceinline__ void ldsm_x4(uint32_t& r0, uint32_t& r1,
                                        uint32_t& r2, uint32_t& r3, const void* p) {
    uint32_t a = (uint32_t)__cvta_generic_to_shared(p);
    asm volatile("ldmatrix.sync.aligned.m8n8.x4.shared.b16 {%0,%1,%2,%3}, [%4];"
                 : "=r"(r0), "=r"(r1), "=r"(r2), "=r"(r3) : "r"(a));
}

// ---------------------------------------------------------------------------
// Prep: emb -> normalized s8 + scales; batch -> s8 + scales.
// Warp per row; each lane owns 16 contiguous values (one uint4 of s8 out).
// ---------------------------------------------------------------------------
__global__ void prep_emb(const float* __restrict__ emb) {
    int row  = blockIdx.x * 8 + (threadIdx.x >> 5);
    int lane = threadIdx.x & 31;
    if (row >= V_TOTAL) return;
    const float4* src = reinterpret_cast<const float4*>(emb + (size_t)row * E_DIM) + lane * 4;
    float v[16];
    float s = 0.f;
#pragma unroll
    for (int i = 0; i < 4; ++i) {
        float4 q = src[i];
        v[i*4] = q.x; v[i*4+1] = q.y; v[i*4+2] = q.z; v[i*4+3] = q.w;
        s += q.x*q.x + q.y*q.y + q.z*q.z + q.w*q.w;
    }
#pragma unroll
    for (int o = 16; o; o >>= 1) s += __shfl_xor_sync(0xffffffffu, s, o);
    float inv = rsqrtf(s);
    float mx = 0.f;
#pragma unroll
    for (int i = 0; i < 16; ++i) mx = fmaxf(mx, fabsf(v[i] * inv));
#pragma unroll
    for (int o = 16; o; o >>= 1) mx = fmaxf(mx, __shfl_xor_sync(0xffffffffu, mx, o));
    float qs = 127.f / mx;
    if (lane == 0) { g_inv[row] = inv; g_es[row] = mx / 127.f; }
    uint32_t w[4];
#pragma unroll
    for (int j = 0; j < 4; ++j) {
        uint32_t pk = 0;
#pragma unroll
        for (int k = 0; k < 4; ++k) {
            int q = __float2int_rn(v[j*4+k] * inv * qs);
            q = max(-127, min(127, q));
            pk |= ((uint32_t)(uint8_t)(int8_t)q) << (k * 8);
        }
        w[j] = pk;
    }
    *reinterpret_cast<uint4*>(g_emb_q + (size_t)row * E_DIM + lane * 16) =
        make_uint4(w[0], w[1], w[2], w[3]);
}

__global__ void prep_batch(const float* __restrict__ batch) {
    int row  = blockIdx.x * 8 + (threadIdx.x >> 5);
    int lane = threadIdx.x & 31;
    if (row >= N_TOK) return;
    const float4* src = reinterpret_cast<const float4*>(batch + (size_t)row * E_DIM) + lane * 4;
    float v[16];
#pragma unroll
    for (int i = 0; i < 4; ++i) {
        float4 q = src[i];
        v[i*4] = q.x; v[i*4+1] = q.y; v[i*4+2] = q.z; v[i*4+3] = q.w;
    }
    float mx = 0.f;
#pragma unroll
    for (int i = 0; i < 16; ++i) mx = fmaxf(mx, fabsf(v[i]));
#pragma unroll
    for (int o = 16; o; o >>= 1) mx = fmaxf(mx, __shfl_xor_sync(0xffffffffu, mx, o));
    float qs = 127.f / mx;
    if (lane == 0) g_bs[row] = mx / 127.f;
    uint32_t w[4];
#pragma unroll
    for (int j = 0; j < 4; ++j) {
        uint32_t pk = 0;
#pragma unroll
        for (int k = 0; k < 4; ++k) {
            int q = __float2int_rn(v[j*4+k] * qs);
            q = max(-127, min(127, q));
            pk |= ((uint32_t)(uint8_t)(int8_t)q) << (k * 8);
        }
        w[j] = pk;
    }
    *reinterpret_cast<uint4*>(g_batch_q + (size_t)row * E_DIM + lane * 16) =
        make_uint4(w[0], w[1], w[2], w[3]);
}

// ---------------------------------------------------------------------------
// Stage 1: s8 IMMA (m16n8k32, s32 accum = exact) + split-max + candidates.
// 4-stage cp.async (64B k-chunks), ldmatrix fragments, warp tile 32x64.
// Grid (VS=9, 32) = 288 CTAs, 2 CTAs/SM -> single wave.
// ---------------------------------------------------------------------------
__global__ __launch_bounds__(256, 2)
void score1() {
    extern __shared__ __align__(16) char dsm[];
    typedef int8_t (*Tile)[128][PADB];
    Tile A_s = reinterpret_cast<Tile>(dsm);                              // [4][128][80]
    Tile B_s = reinterpret_cast<Tile>(dsm + NSTAGE * STAGE_BYTES);

    __shared__ int   row_max[128];
    __shared__ float es_s[128];

    const int vs   = blockIdx.x;
    const int tb   = blockIdx.y;
    const int tid  = threadIdx.x;
    const int lane = tid & 31;
    const int w    = tid >> 5;
    const int wm   = w >> 1;          // 0..3 (M warp)
    const int wn   = w & 1;           // 0..1 (N warp)
    const int g    = lane >> 2;       // 0..7
    const int tg   = lane & 3;        // 0..3

    const int lr  = (lane & 7) + ((lane >> 3) & 1) * 8;  // ldmatrix row in 16
    const int lcb = ((lane >> 4) & 1) * 16;              // byte offset 0/16

    const int v_begin = vs * SPLIT;
    const int v_lim   = min(v_begin + SPLIT, V_TOTAL);
    const int ntiles  = (v_lim - v_begin + 127) >> 7;

    if (tid < 128) {
        row_max[tid] = 0x80000000;
        g_cnt[(tb * 128 + tid) * VS + vs] = 0;   // per-launch reset (graph-safe)
    }
    __syncthreads();

    // per-thread token scales (rows owned by this thread, fixed across tiles)
    float sbr[4];
#pragma unroll
    for (int ri = 0; ri < 4; ++ri) {
        int r = wm * 32 + (ri >> 1) * 16 + g + (ri & 1) * 8;
        sbr[ri] = g_bs[tb * 128 + r];
    }

    const int l_row0 = (tid * 2)     >> 2, l_q0 = (tid * 2)     & 3;
    const int l_row1 = (tid * 2 + 1) >> 2, l_q1 = (tid * 2 + 1) & 3;

    for (int t = 0; t < ntiles; ++t) {
        const int v0 = v_begin + t * 128;

        if (tid < 128) {
            int v = v0 + tid;
            es_s[tid] = (v < v_lim) ? g_es[v] : 0.f;
        }

        int c[2][8][4];
#pragma unroll
        for (int mt = 0; mt < 2; ++mt)
#pragma unroll
            for (int nt = 0; nt < 8; ++nt)
#pragma unroll
                for (int q = 0; q < 4; ++q) c[mt][nt][q] = 0;

        auto load_stage = [&](int s, int kc) {
            int k0 = kc * 64;
            cpa16(&A_s[s][l_row0][l_q0 * 16],
                  g_batch_q + (size_t)(tb * 128 + l_row0) * E_DIM + k0 + l_q0 * 16, 16);
            cpa16(&A_s[s][l_row1][l_q1 * 16],
                  g_batch_q + (size_t)(tb * 128 + l_row1) * E_DIM + k0 + l_q1 * 16, 16);
            int n0 = v0 + l_row0, n1 = v0 + l_row1;
            cpa16(&B_s[s][l_row0][l_q0 * 16],
                  g_emb_q + (size_t)min(n0, V_TOTAL - 1) * E_DIM + k0 + l_q0 * 16,
                  (n0 < v_lim) ? 16 : 0);
            cpa16(&B_s[s][l_row1][l_q1 * 16],
                  g_emb_q + (size_t)min(n1, V_TOTAL - 1) * E_DIM + k0 + l_q1 * 16,
                  (n1 < v_lim) ? 16 : 0);
        };

#pragma unroll
        for (int p = 0; p < NSTAGE - 1; ++p) { load_stage(p, p); CPA_COMMIT(); }

        for (int kc = 0; kc < NKC; ++kc) {
            const int cur = kc & (NSTAGE - 1);

            if (kc < NKC - 2)       cpa_wait<2>();
            else if (kc == NKC - 2) cpa_wait<1>();
            else                    cpa_wait<0>();
            __syncthreads();

#pragma unroll
            for (int ki = 0; ki < 2; ++ki) {
                const int kb = ki * 32;                  // byte offset of k32 step
                uint32_t a[2][4], b[8][2];
#pragma unroll
                for (int mt = 0; mt < 2; ++mt)
                    ldsm_x4(a[mt][0], a[mt][1], a[mt][2], a[mt][3],
                            &A_s[cur][wm * 32 + mt * 16 + lr][kb + lcb]);
#pragma unroll
                for (int ntp = 0; ntp < 4; ++ntp) {
                    uint32_t m0, m1, m2, m3;
                    ldsm_x4(m0, m1, m2, m3,
                            &B_s[cur][wn * 64 + ntp * 16 + lr][kb + lcb]);
                    b[ntp * 2][0]     = m0;  b[ntp * 2 + 1][0] = m1;
                    b[ntp * 2][1]     = m2;  b[ntp * 2 + 1][1] = m3;
                }
#pragma unroll
                for (int mt = 0; mt < 2; ++mt)
#pragma unroll
                    for (int nt = 0; nt < 8; ++nt)
                        asm volatile(
                            "mma.sync.aligned.m16n8k32.row.col.s32.s8.s8.s32 "
                            "{%0,%1,%2,%3},{%4,%5,%6,%7},{%8,%9},{%0,%1,%2,%3};\n"
                            : "+r"(c[mt][nt][0]), "+r"(c[mt][nt][1]),
                              "+r"(c[mt][nt][2]), "+r"(c[mt][nt][3])
                            : "r"(a[mt][0]), "r"(a[mt][1]), "r"(a[mt][2]), "r"(a[mt][3]),
                              "r"(b[nt][0]), "r"(b[nt][1]));
            }

            if (kc + NSTAGE - 1 < NKC) {
                load_stage((kc + NSTAGE - 1) & (NSTAGE - 1), kc + NSTAGE - 1);
                CPA_COMMIT();
            }
        }

        // ---- epilogue: dequant s = int * es[v] * sb[token] (= b . e_hat),
        //      split running max, candidate insert ----
        float cf[2][8][4];
#pragma unroll
        for (int mt = 0; mt < 2; ++mt)
#pragma unroll
            for (int nt = 0; nt < 8; ++nt) {
                int nl = wn * 64 + nt * 8 + tg * 2;
#pragma unroll
                for (int q = 0; q < 4; ++q) {
                    int col = nl + (q & 1);
                    int v   = v0 + col;
                    int ri  = mt * 2 + (q >> 1);
                    float s = (float)c[mt][nt][q] * es_s[col] * sbr[ri];
                    cf[mt][nt][q] = (v < v_lim) ? s : -1e30f;
                }
            }

        float rmax[4] = {-1e30f, -1e30f, -1e30f, -1e30f};
#pragma unroll
        for (int mt = 0; mt < 2; ++mt)
#pragma unroll
            for (int nt = 0; nt < 8; ++nt)
#pragma unroll
                for (int q = 0; q < 4; ++q) {
                    int ri = mt * 2 + (q >> 1);
                    rmax[ri] = fmaxf(rmax[ri], cf[mt][nt][q]);
                }
#pragma unroll
        for (int ri = 0; ri < 4; ++ri) {
            int r = wm * 32 + (ri >> 1) * 16 + g + (ri & 1) * 8;
            int key = __float_as_int(rmax[ri]);
            key = (key >= 0) ? key : (key ^ 0x7FFFFFFF);
            atomicMax(&row_max[r], key);
        }
        __syncthreads();

        float thr[4];
#pragma unroll
        for (int ri = 0; ri < 4; ++ri) {
            int r = wm * 32 + (ri >> 1) * 16 + g + (ri & 1) * 8;
            int key = row_max[r];
            float m = __int_as_float((key >= 0) ? key : (key ^ 0x7FFFFFFF));
            thr[ri] = m - MARGIN;
        }
#pragma unroll
        for (int mt = 0; mt < 2; ++mt)
#pragma unroll
            for (int nt = 0; nt < 8; ++nt)
#pragma unroll
                for (int q = 0; q < 4; ++q) {
                    int ri = mt * 2 + (q >> 1);
                    float s = cf[mt][nt][q];
                    if (s > thr[ri]) {
                        int col   = wn * 64 + nt * 8 + tg * 2 + (q & 1);
                        int v     = v0 + col;
                        int token = tb * 128 + wm * 32 + (ri >> 1) * 16 + g + (ri & 1) * 8;
                        int slot  = atomicAdd(&g_cnt[token * VS + vs], 1);
                        if (slot < CAP) g_cand[(token * VS + vs) * CAP + slot] = v;
                    }
                }
        __syncthreads();   // protect es_s/smem reuse by next tile
    }
}

// ---------------------------------------------------------------------------
// Stage 2: exact fp32 rescore; warp per token; lowest-index tie-break.
// ---------------------------------------------------------------------------
__global__ void rescore(const float* __restrict__ batch, const float* __restrict__ emb,
                        float* __restrict__ out) {
    int warp = (blockIdx.x * blockDim.x + threadIdx.x) >> 5;
    int lane = threadIdx.x & 31;
    if (warp >= N_TOK) return;
    const int t = warp;

    float bb[16];
#pragma unroll
    for (int j = 0; j < 16; ++j) bb[j] = batch[(size_t)t * E_DIM + lane + 32 * j];

    float bestv = -1e30f;
    int   besti = 0x7fffffff;
    for (int vs = 0; vs < VS; ++vs) {
        int c = g_cnt[t * VS + vs];
        if (c > CAP) c = CAP;
        for (int i = 0; i < c; ++i) {
            int v = g_cand[(t * VS + vs) * CAP + i];
            const float* e = emb + (size_t)v * E_DIM;
            float s = 0.f;
#pragma unroll
            for (int j = 0; j < 16; ++j) s += bb[j] * e[lane + 32 * j];
#pragma unroll
            for (int o = 16; o; o >>= 1) s += __shfl_xor_sync(0xffffffffu, s, o);
            s *= g_inv[v];
            if (s > bestv || (s == bestv && v < besti)) { bestv = s; besti = v; }
        }
    }
    if (lane == 0) out[t] = (float)besti;
}

// ---------------------------------------------------------------------------
extern "C" void kernel_launch(void* const* d_in, const int* in_sizes, int n_in,
                              void* d_out, int out_size) {
    const float* batch = nullptr;
    const float* emb   = nullptr;
    for (int i = 0; i < n_in; ++i) {
        if (in_sizes[i] == BATCH_ELEMS)    batch = (const float*)d_in[i];
        else if (in_sizes[i] == EMB_ELEMS) emb   = (const float*)d_in[i];
    }
    if (!batch) batch = (const float*)d_in[0];
    if (!emb)   emb   = (const float*)d_in[1];

    float* out = (float*)d_out;   // [8,512] indices written as f32 values

    cudaFuncSetAttribute(score1, cudaFuncAttributeMaxDynamicSharedMemorySize, DSMEM_BYTES);

    prep_emb<<<(V_TOTAL + 7) / 8, 256>>>(emb);
    prep_batch<<<(N_TOK + 7) / 8, 256>>>(batch);

    dim3 grid(VS, N_TOK / 128);   // 9 x 32 = 288 CTAs -> one wave at 2 CTA/SM
    score1<<<grid, 256, DSMEM_BYTES>>>();

    rescore<<<(N_TOK * 32 + 255) / 256, 256>>>(batch, emb, out);
}